// round 2
// baseline (speedup 1.0000x reference)
#include <cuda_runtime.h>
#include <math.h>

#define HW 65536
#define CIN 256
#define CMID 64

// ---- scratch (device globals; allocation is forbidden) ----
__device__ float g_y[4 * CMID * HW];      // after input conv1x1  (64 MiB)
__device__ float g_edge[4 * CMID * HW];   // raw edge map         (64 MiB)
__device__ float g_sums[4 * CMID];        // per-(b,c) raw-edge sums
__device__ unsigned int g_maxbits;        // global max (float bits, all vals >= 0)
__device__ float g_weff[4 * CMID * CMID]; // folded output weights per batch

// ---- packed fp32x2 helpers (Blackwell) ----
__device__ __forceinline__ unsigned long long pack2(float a, float b) {
    unsigned long long r;
    asm("mov.b64 %0, {%1,%2};" : "=l"(r) : "f"(a), "f"(b));
    return r;
}
__device__ __forceinline__ unsigned long long fma2(unsigned long long a,
                                                   unsigned long long b,
                                                   unsigned long long c) {
    unsigned long long d;
    asm("fma.rn.f32x2 %0, %1, %2, %3;" : "=l"(d) : "l"(a), "l"(b), "l"(c));
    return d;
}

// ---------------------------------------------------------------------------
__global__ void k_init() {
    int t = threadIdx.x;
    if (t < 256) g_sums[t] = 0.f;
    if (t == 0) g_maxbits = 0u;
}

// ---------------------------------------------------------------------------
// conv1x1 in: y[b,o,p] = b_in[o] + sum_c w_in[o,c] * x[b,c,p]
// f32x2: each thread = 2 adjacent pixels x 32 outputs. Weights in smem as
// duplicated (w,w) pairs so one LDS.128 feeds two FFMA2.
__global__ void __launch_bounds__(256) k_conv_in(const float* __restrict__ x,
                                                 const float* __restrict__ w,
                                                 const float* __restrict__ bias) {
    __shared__ float2 ws2[64][64];   // 32 KB: 64 outputs x 64 channels (one stage)
    int tid   = threadIdx.x;
    int half  = tid >> 7;            // 0 -> outputs [0,32), 1 -> [32,64)
    int t     = tid & 127;
    int obase = half * 32;
    int p0    = blockIdx.x * 256 + 2 * t;   // pixel pair start
    int b     = p0 >> 16;
    int pix   = p0 & 65535;
    const float* xb = x + (size_t)b * CIN * HW + pix;

    unsigned long long acc[32];
#pragma unroll
    for (int o = 0; o < 32; ++o) {
        float bv = bias[obase + o];
        acc[o] = pack2(bv, bv);
    }

    for (int s = 0; s < 4; ++s) {
        for (int i = tid; i < 64 * 64; i += 256) {
            int o = i >> 6, c = i & 63;
            float wv = w[o * CIN + s * 64 + c];
            ws2[o][c] = make_float2(wv, wv);
        }
        __syncthreads();
        const float* xp = xb + (size_t)(s * 64) * HW;
#pragma unroll 4
        for (int c = 0; c < 64; c += 2) {
            unsigned long long xv0 = *(const unsigned long long*)(xp + (size_t)c * HW);
            unsigned long long xv1 = *(const unsigned long long*)(xp + (size_t)(c + 1) * HW);
#pragma unroll
            for (int o = 0; o < 32; ++o) {
                ulonglong2 wq = *(const ulonglong2*)&ws2[obase + o][c];
                acc[o] = fma2(wq.x, xv0, acc[o]);
                acc[o] = fma2(wq.y, xv1, acc[o]);
            }
        }
        __syncthreads();
    }
    float* yp = g_y + (size_t)b * CMID * HW + pix;
#pragma unroll
    for (int o = 0; o < 32; ++o)
        *(unsigned long long*)(yp + (size_t)(obase + o) * HW) = acc[o];
}

// ---------------------------------------------------------------------------
// Fused depthwise stage: separable 5x5 gaussian -> scharr0/scharr90/laplacian
// -> raw edge + per-plane sum + global max. One block per 32x32 tile per plane.
__global__ void __launch_bounds__(256) k_edge() {
    __shared__ float ys[38][40];  // y with halo 3
    __shared__ float ts[34][40];  // vertical gaussian pass
    __shared__ float ss[34][36];  // smoothed (sm) with halo 1
    __shared__ float rs[8], rm[8];

    int tid   = threadIdx.x;
    int plane = blockIdx.y;                 // b*64 + c
    int tile  = blockIdx.x;                 // 0..63
    int ty0 = (tile >> 3) * 32;
    int tx0 = (tile & 7) * 32;
    const float* yp = g_y + (size_t)plane * HW;

    for (int i = tid; i < 38 * 38; i += 256) {
        int r = i / 38, c = i - r * 38;
        int gy = ty0 - 3 + r, gx = tx0 - 3 + c;
        float v = 0.f;
        if ((unsigned)gy < 256u && (unsigned)gx < 256u) v = yp[gy * 256 + gx];
        ys[r][c] = v;
    }
    __syncthreads();

    float g1 = expf(-0.125f), g2 = expf(-0.5f);
    float sg = 1.f + 2.f * g1 + 2.f * g2;
    float invS = 1.f / (sg * sg);

    for (int i = tid; i < 34 * 38; i += 256) {
        int r = i / 38, c = i - r * 38;
        ts[r][c] = g2 * (ys[r][c] + ys[r + 4][c]) +
                   g1 * (ys[r + 1][c] + ys[r + 3][c]) + ys[r + 2][c];
    }
    __syncthreads();

    for (int i = tid; i < 34 * 34; i += 256) {
        int r = i / 34, c = i - r * 34;
        float v = g2 * (ts[r][c] + ts[r][c + 4]) +
                  g1 * (ts[r][c + 1] + ts[r][c + 3]) + ts[r][c + 2];
        v *= invS;
        int gy = ty0 - 1 + r, gx = tx0 - 1 + c;
        if ((unsigned)gy >= 256u || (unsigned)gx >= 256u) v = 0.f;
        ss[r][c] = v;
    }
    __syncthreads();

    int col = tid & 31;
    int rb  = tid >> 5;
    float lsum = 0.f, lmax = 0.f;
    float* ep = g_edge + (size_t)plane * HW;
#pragma unroll
    for (int q = 0; q < 4; ++q) {
        int r = rb + q * 8;
        float a  = ss[r][col],     bb = ss[r][col + 1],     cv = ss[r][col + 2];
        float d  = ss[r + 1][col], e  = ss[r + 1][col + 1], f  = ss[r + 1][col + 2];
        float g  = ss[r + 2][col], h  = ss[r + 2][col + 1], ii = ss[r + 2][col + 2];
        float g0  = 3.f * (a - cv) + 10.f * (d - f) + 3.f * (g - ii);
        float g90 = 3.f * (a - g)  + 10.f * (bb - h) + 3.f * (cv - ii);
        float lap = 4.f * e - bb - d - f - h;
        float edge = fmaxf(fabsf(g0), fabsf(g90)) + 0.1f * fabsf(lap);
        ep[(ty0 + r) * 256 + tx0 + col] = edge;
        lsum += edge;
        lmax = fmaxf(lmax, edge);
    }

#pragma unroll
    for (int off = 16; off; off >>= 1) {
        lsum += __shfl_down_sync(0xffffffffu, lsum, off);
        lmax = fmaxf(lmax, __shfl_down_sync(0xffffffffu, lmax, off));
    }
    int wid = tid >> 5, lane = tid & 31;
    if (lane == 0) { rs[wid] = lsum; rm[wid] = lmax; }
    __syncthreads();
    if (tid == 0) {
        float s = 0.f, m = 0.f;
#pragma unroll
        for (int w2 = 0; w2 < 8; ++w2) { s += rs[w2]; m = fmaxf(m, rm[w2]); }
        atomicAdd(&g_sums[plane], s);
        atomicMax(&g_maxbits, __float_as_uint(m));
    }
}

// ---------------------------------------------------------------------------
// SE head + weight folding. 1024 threads: first 256 compute scale, all write weff.
__global__ void __launch_bounds__(1024) k_se(const float* __restrict__ w_fc1,
                                             const float* __restrict__ b_fc1,
                                             const float* __restrict__ w_fc2,
                                             const float* __restrict__ b_fc2,
                                             const float* __restrict__ w_out) {
    __shared__ float pooled[4][64];
    __shared__ float fmul[4][64];
    int tid = threadIdx.x;
    float maxv, inv;
    if (tid < 256) {
        maxv = __uint_as_float(g_maxbits);
        inv = 1.f / (maxv + 1e-8f);
        int b = tid >> 6, c = tid & 63;
        pooled[b][c] = g_sums[tid] * (1.f / 65536.f) * inv;
    }
    __syncthreads();
    if (tid < 256) {
        int b = tid >> 6, c = tid & 63;
        float h[4];
#pragma unroll
        for (int j = 0; j < 4; ++j) {
            float s = b_fc1[j];
            for (int cc = 0; cc < 64; ++cc) s = fmaf(w_fc1[j * 64 + cc], pooled[b][cc], s);
            h[j] = fmaxf(s, 0.f);
        }
        float sc = b_fc2[c];
#pragma unroll
        for (int j = 0; j < 4; ++j) sc = fmaf(w_fc2[c * 4 + j], h[j], sc);
        sc = 1.f / (1.f + expf(-sc));
        fmul[b][c] = sc * inv;
    }
    __syncthreads();
    // weff[(b*64+o)*64+c] = w_out[o*64+c] * fmul[b][c]
    for (int i = tid; i < 4 * 64 * 64; i += 1024) {
        int c = i & 63;
        int o = (i >> 6) & 63;
        int b = i >> 12;
        g_weff[i] = w_out[o * 64 + c] * fmul[b][c];
    }
}

// ---------------------------------------------------------------------------
// conv1x1 out with folded weights, f32x2: 2 pixels x 32 outputs per thread.
__global__ void __launch_bounds__(256) k_conv_out(const float* __restrict__ bias,
                                                  float* __restrict__ out) {
    __shared__ float2 ws2[64][64];   // 32 KB duplicated pairs
    int tid   = threadIdx.x;
    int half  = tid >> 7;
    int t     = tid & 127;
    int obase = half * 32;
    int p0    = blockIdx.x * 256 + 2 * t;
    int b     = p0 >> 16;
    int pix   = p0 & 65535;

    const float* wb = g_weff + b * 4096;
    for (int i = tid; i < 64 * 64; i += 256) {
        float wv = wb[i];
        ws2[i >> 6][i & 63] = make_float2(wv, wv);
    }
    __syncthreads();

    unsigned long long acc[32];
#pragma unroll
    for (int o = 0; o < 32; ++o) {
        float bv = bias[obase + o];
        acc[o] = pack2(bv, bv);
    }

    const float* ep = g_edge + (size_t)b * CMID * HW + pix;
#pragma unroll 4
    for (int c = 0; c < 64; c += 2) {
        unsigned long long e0 = *(const unsigned long long*)(ep + (size_t)c * HW);
        unsigned long long e1 = *(const unsigned long long*)(ep + (size_t)(c + 1) * HW);
#pragma unroll
        for (int o = 0; o < 32; ++o) {
            ulonglong2 wq = *(const ulonglong2*)&ws2[obase + o][c];
            acc[o] = fma2(wq.x, e0, acc[o]);
            acc[o] = fma2(wq.y, e1, acc[o]);
        }
    }
    float* op = out + (size_t)b * CMID * HW + pix;
#pragma unroll
    for (int o = 0; o < 32; ++o)
        *(unsigned long long*)(op + (size_t)(obase + o) * HW) = acc[o];
}

// ---------------------------------------------------------------------------
extern "C" void kernel_launch(void* const* d_in, const int* in_sizes, int n_in,
                              void* d_out, int out_size) {
    const float* x     = (const float*)d_in[0];
    const float* w_in  = (const float*)d_in[1];
    const float* b_in  = (const float*)d_in[2];
    const float* w_fc1 = (const float*)d_in[3];
    const float* b_fc1 = (const float*)d_in[4];
    const float* w_fc2 = (const float*)d_in[5];
    const float* b_fc2 = (const float*)d_in[6];
    const float* w_out = (const float*)d_in[7];
    const float* b_out = (const float*)d_in[8];
    float* out = (float*)d_out;

    k_init<<<1, 256>>>();
    k_conv_in<<<1024, 256>>>(x, w_in, b_in);
    k_edge<<<dim3(64, 256), 256>>>();
    k_se<<<1, 1024>>>(w_fc1, b_fc1, w_fc2, b_fc2, w_out);
    k_conv_out<<<1024, 256>>>(b_out, out);
}

// round 4
// speedup vs baseline: 2.3276x; 2.3276x over previous
#include <cuda_runtime.h>
#include <cuda_bf16.h>
#include <math.h>

#define HW 65536
#define CMID 64

// ---- scratch (device globals; allocation is forbidden) ----
__device__ float g_y[4 * CMID * HW];      // after input conv1x1  (64 MiB)
__device__ float g_edge[4 * CMID * HW];   // raw edge map         (64 MiB)
__device__ float g_sums[4 * CMID];        // per-(b,c) raw-edge sums
__device__ unsigned int g_maxbits;        // global max (float bits, all >= 0)

// ---- dynamic smem layout (bytes) ----
#define XPITCH 136                        // bf16 elems per X row (128 + 8 pad, 272B = 17*16)
#define WPITCH 72                         // bf16 elems per W row (64 + 8 pad, 144B = 9*16)
#define XH_OFF 0                          // 64 x 136 x 2 = 17408
#define XL_OFF 17408
#define WH_OFF 34816                      // 64 x 72 x 2 = 9216
#define WL_OFF 44032
#define FM_OFF 53248                      // fmul[64] (FOLD only)
#define PL_OFF 53504                      // pooled[64]
#define HH_OFF 53760                      // h[4]
#define SMEM_SZ 53792

// ============================ PTX helpers ==================================
__device__ __forceinline__ unsigned smem_u32(const void* p) {
    unsigned a;
    asm("{ .reg .u64 t; cvta.to.shared.u64 t, %1; cvt.u32.u64 %0, t; }" : "=r"(a) : "l"(p));
    return a;
}
__device__ __forceinline__ void ldsm4t(unsigned& r0, unsigned& r1, unsigned& r2,
                                       unsigned& r3, unsigned a) {
    asm volatile("ldmatrix.sync.aligned.m8n8.x4.trans.shared.b16 {%0,%1,%2,%3}, [%4];"
                 : "=r"(r0), "=r"(r1), "=r"(r2), "=r"(r3) : "r"(a));
}
__device__ __forceinline__ void ldsm2(unsigned& r0, unsigned& r1, unsigned a) {
    asm volatile("ldmatrix.sync.aligned.m8n8.x2.shared.b16 {%0,%1}, [%2];"
                 : "=r"(r0), "=r"(r1) : "r"(a));
}
__device__ __forceinline__ void mma16816(float* d, const unsigned* a, const unsigned* b) {
    asm volatile("mma.sync.aligned.m16n8k16.row.col.f32.bf16.bf16.f32 "
                 "{%0,%1,%2,%3},{%4,%5,%6,%7},{%8,%9},{%0,%1,%2,%3};"
                 : "+f"(d[0]), "+f"(d[1]), "+f"(d[2]), "+f"(d[3])
                 : "r"(a[0]), "r"(a[1]), "r"(a[2]), "r"(a[3]), "r"(b[0]), "r"(b[1]));
}
__device__ __forceinline__ unsigned pk(float a, float b) {
    __nv_bfloat162 t(__float2bfloat16(a), __float2bfloat16(b));
    return *(unsigned*)&t;
}

// ===========================================================================
// conv1x1 via mma.sync bf16 3-term split. Tile: 128 pix x 64 out, K=CHUNKS*64.
// FOLD=1: fuse SE head (compute per-channel fmul from g_sums/g_maxbits, fold
// into W staging). FOLD=0: also zero g_sums/g_maxbits from block 0.
template <int CHUNKS, int FOLD>
__global__ void __launch_bounds__(256) k_conv(
    const float* __restrict__ src, int cin,
    const float* __restrict__ wsrc, int wstride,
    const float* __restrict__ bias, float* __restrict__ dst,
    const float* __restrict__ w_fc1, const float* __restrict__ b_fc1,
    const float* __restrict__ w_fc2, const float* __restrict__ b_fc2) {
    extern __shared__ char sm[];
    unsigned smb = smem_u32(sm);
    int tid = threadIdx.x;
    int w   = tid >> 5, lane = tid & 31;

    int t    = blockIdx.x;
    int b    = t >> 9;           // 512 tiles per batch
    int pix0 = (t & 511) << 7;   // 128 pixels per tile

    if (!FOLD && blockIdx.x == 0) {   // init for this replay's edge stage
        if (tid < 256) g_sums[tid] = 0.f;
        if (tid == 0) g_maxbits = 0u;
    }

    if (FOLD) {
        float* pooled = (float*)(sm + PL_OFF);
        float* hh     = (float*)(sm + HH_OFF);
        float* fm     = (float*)(sm + FM_OFF);
        float inv = 1.f / (__uint_as_float(g_maxbits) + 1e-8f);
        if (tid < 64) pooled[tid] = g_sums[b * 64 + tid] * (1.f / 65536.f) * inv;
        __syncthreads();
        if (tid < 4) {
            float s = b_fc1[tid];
            for (int cc = 0; cc < 64; ++cc) s = fmaf(w_fc1[tid * 64 + cc], pooled[cc], s);
            hh[tid] = fmaxf(s, 0.f);
        }
        __syncthreads();
        if (tid < 64) {
            float sc = b_fc2[tid];
#pragma unroll
            for (int j = 0; j < 4; ++j) sc = fmaf(w_fc2[tid * 4 + j], hh[j], sc);
            fm[tid] = inv / (1.f + expf(-sc));
        }
        __syncthreads();
    }

    const float* srcb = src + (size_t)b * cin * HW + pix0;

    float acc[8][4];
#pragma unroll
    for (int nt = 0; nt < 8; ++nt)
#pragma unroll
        for (int i = 0; i < 4; ++i) acc[nt][i] = 0.f;

    // ldmatrix address components
    int arow = (lane & 7) + ((lane >> 4) << 3);
    int acol = (w << 4) + (((lane >> 3) & 1) << 3);
    int brow = lane & 7;
    int bcol = ((lane >> 3) & 1) << 3;

    for (int s = 0; s < CHUNKS; ++s) {
        // ---- stage X chunk: gmem [c][pix] fp32 -> smem bf16 hi/lo [c][pix]
        {
            int c = tid >> 2, q = tid & 3;
            const float* xc = srcb + (size_t)(s * 64 + c) * HW;
            unsigned rowb = smb + (unsigned)((c * XPITCH) * 2);
#pragma unroll
            for (int j = 0; j < 4; ++j) {
                int p = q * 32 + j * 8;
                float4 v0 = *(const float4*)(xc + p);
                float4 v1 = *(const float4*)(xc + p + 4);
                float xs[8] = {v0.x, v0.y, v0.z, v0.w, v1.x, v1.y, v1.z, v1.w};
                float hf[8], lf[8];
#pragma unroll
                for (int i = 0; i < 8; ++i) {
                    hf[i] = __bfloat162float(__float2bfloat16(xs[i]));
                    lf[i] = xs[i] - hf[i];
                }
                uint4 hv = make_uint4(pk(hf[0], hf[1]), pk(hf[2], hf[3]),
                                      pk(hf[4], hf[5]), pk(hf[6], hf[7]));
                uint4 lv = make_uint4(pk(lf[0], lf[1]), pk(lf[2], lf[3]),
                                      pk(lf[4], lf[5]), pk(lf[6], lf[7]));
                unsigned off = (unsigned)(p * 2);
                *(uint4*)(sm + XH_OFF + (c * XPITCH + p) * 2) = hv;
                *(uint4*)(sm + XL_OFF + (c * XPITCH + p) * 2) = lv;
                (void)rowb; (void)off;
            }
        }
        // ---- stage W chunk: [64 out][64 ch] fp32 -> bf16 hi/lo (pitch 72)
        {
            const float* fm = (const float*)(sm + FM_OFF);
#pragma unroll
            for (int k = 0; k < 16; ++k) {
                int i = tid + k * 256;
                int o = i >> 6, cc = i & 63;
                float wv = wsrc[o * wstride + s * 64 + cc];
                if (FOLD) wv *= fm[cc];
                float hv = __bfloat162float(__float2bfloat16(wv));
                float lv = wv - hv;
                *(__nv_bfloat16*)(sm + WH_OFF + (o * WPITCH + cc) * 2) = __float2bfloat16(hv);
                *(__nv_bfloat16*)(sm + WL_OFF + (o * WPITCH + cc) * 2) = __float2bfloat16(lv);
            }
        }
        __syncthreads();

        // ---- MMA: 4 k-steps of 16
#pragma unroll
        for (int ks = 0; ks < 4; ++ks) {
            unsigned ah[4], al[4];
            unsigned aoff = (unsigned)(((ks * 16 + arow) * XPITCH + acol) * 2);
            ldsm4t(ah[0], ah[1], ah[2], ah[3], smb + XH_OFF + aoff);
            ldsm4t(al[0], al[1], al[2], al[3], smb + XL_OFF + aoff);
#pragma unroll
            for (int nt = 0; nt < 8; ++nt) {
                unsigned bh[2], bl[2];
                unsigned boff = (unsigned)(((nt * 8 + brow) * WPITCH + ks * 16 + bcol) * 2);
                ldsm2(bh[0], bh[1], smb + WH_OFF + boff);
                ldsm2(bl[0], bl[1], smb + WL_OFF + boff);
                mma16816(acc[nt], ah, bh);
                mma16816(acc[nt], al, bh);
                mma16816(acc[nt], ah, bl);
            }
        }
        __syncthreads();
    }

    // ---- epilogue: C[m=pix][n=out] fragments -> dst[o][pix] + bias
    int g  = lane >> 2;
    int t2 = (lane & 3) * 2;
    float* dp = dst + (size_t)b * CMID * HW + pix0 + w * 16;
#pragma unroll
    for (int nt = 0; nt < 8; ++nt) {
        int o0 = nt * 8 + t2;
        float b0 = __ldg(bias + o0), b1 = __ldg(bias + o0 + 1);
        dp[(size_t)o0 * HW + g]           = acc[nt][0] + b0;
        dp[(size_t)(o0 + 1) * HW + g]     = acc[nt][1] + b1;
        dp[(size_t)o0 * HW + g + 8]       = acc[nt][2] + b0;
        dp[(size_t)(o0 + 1) * HW + g + 8] = acc[nt][3] + b1;
    }
}

// ---------------------------------------------------------------------------
// Fused depthwise stage (identical to the 526us run)
__global__ void __launch_bounds__(256) k_edge() {
    __shared__ float ys[38][40];
    __shared__ float ts[34][40];
    __shared__ float ss[34][36];
    __shared__ float rs[8], rm[8];

    int tid   = threadIdx.x;
    int plane = blockIdx.y;
    int tile  = blockIdx.x;
    int ty0 = (tile >> 3) * 32;
    int tx0 = (tile & 7) * 32;
    const float* yp = g_y + (size_t)plane * HW;

    for (int i = tid; i < 38 * 38; i += 256) {
        int r = i / 38, c = i - r * 38;
        int gy = ty0 - 3 + r, gx = tx0 - 3 + c;
        float v = 0.f;
        if ((unsigned)gy < 256u && (unsigned)gx < 256u) v = yp[gy * 256 + gx];
        ys[r][c] = v;
    }
    __syncthreads();

    float g1 = expf(-0.125f), g2 = expf(-0.5f);
    float sg = 1.f + 2.f * g1 + 2.f * g2;
    float invS = 1.f / (sg * sg);

    for (int i = tid; i < 34 * 38; i += 256) {
        int r = i / 38, c = i - r * 38;
        ts[r][c] = g2 * (ys[r][c] + ys[r + 4][c]) +
                   g1 * (ys[r + 1][c] + ys[r + 3][c]) + ys[r + 2][c];
    }
    __syncthreads();

    for (int i = tid; i < 34 * 34; i += 256) {
        int r = i / 34, c = i - r * 34;
        float v = g2 * (ts[r][c] + ts[r][c + 4]) +
                  g1 * (ts[r][c + 1] + ts[r][c + 3]) + ts[r][c + 2];
        v *= invS;
        int gy = ty0 - 1 + r, gx = tx0 - 1 + c;
        if ((unsigned)gy >= 256u || (unsigned)gx >= 256u) v = 0.f;
        ss[r][c] = v;
    }
    __syncthreads();

    int col = tid & 31;
    int rb  = tid >> 5;
    float lsum = 0.f, lmax = 0.f;
    float* ep = g_edge + (size_t)plane * HW;
#pragma unroll
    for (int q = 0; q < 4; ++q) {
        int r = rb + q * 8;
        float a  = ss[r][col],     bb = ss[r][col + 1],     cv = ss[r][col + 2];
        float d  = ss[r + 1][col], e  = ss[r + 1][col + 1], f  = ss[r + 1][col + 2];
        float g  = ss[r + 2][col], h  = ss[r + 2][col + 1], ii = ss[r + 2][col + 2];
        float g0  = 3.f * (a - cv) + 10.f * (d - f) + 3.f * (g - ii);
        float g90 = 3.f * (a - g)  + 10.f * (bb - h) + 3.f * (cv - ii);
        float lap = 4.f * e - bb - d - f - h;
        float edge = fmaxf(fabsf(g0), fabsf(g90)) + 0.1f * fabsf(lap);
        ep[(ty0 + r) * 256 + tx0 + col] = edge;
        lsum += edge;
        lmax = fmaxf(lmax, edge);
    }

#pragma unroll
    for (int off = 16; off; off >>= 1) {
        lsum += __shfl_down_sync(0xffffffffu, lsum, off);
        lmax = fmaxf(lmax, __shfl_down_sync(0xffffffffu, lmax, off));
    }
    int wid = tid >> 5, lane = tid & 31;
    if (lane == 0) { rs[wid] = lsum; rm[wid] = lmax; }
    __syncthreads();
    if (tid == 0) {
        float s = 0.f, m = 0.f;
#pragma unroll
        for (int w2 = 0; w2 < 8; ++w2) { s += rs[w2]; m = fmaxf(m, rm[w2]); }
        atomicAdd(&g_sums[plane], s);
        atomicMax(&g_maxbits, __float_as_uint(m));
    }
}

// ---------------------------------------------------------------------------
extern "C" void kernel_launch(void* const* d_in, const int* in_sizes, int n_in,
                              void* d_out, int out_size) {
    const float* x     = (const float*)d_in[0];
    const float* w_in  = (const float*)d_in[1];
    const float* b_in  = (const float*)d_in[2];
    const float* w_fc1 = (const float*)d_in[3];
    const float* b_fc1 = (const float*)d_in[4];
    const float* w_fc2 = (const float*)d_in[5];
    const float* b_fc2 = (const float*)d_in[6];
    const float* w_out = (const float*)d_in[7];
    const float* b_out = (const float*)d_in[8];
    float* out = (float*)d_out;

    cudaFuncSetAttribute(k_conv<4, 0>, cudaFuncAttributeMaxDynamicSharedMemorySize, SMEM_SZ);
    cudaFuncSetAttribute(k_conv<1, 1>, cudaFuncAttributeMaxDynamicSharedMemorySize, SMEM_SZ);

    float* gy    = nullptr;
    float* gedge = nullptr;
    cudaGetSymbolAddress((void**)&gy, g_y);
    cudaGetSymbolAddress((void**)&gedge, g_edge);

    // conv_in: K=256 (4 chunks), also zeroes g_sums/g_maxbits for this replay
    k_conv<4, 0><<<2048, 256, SMEM_SZ>>>(x, 256, w_in, 256, b_in, gy,
                                         nullptr, nullptr, nullptr, nullptr);
    k_edge<<<dim3(64, 256), 256>>>();
    // conv_out: K=64, SE head fused + folded into W staging
    k_conv<1, 1><<<2048, 256, SMEM_SZ>>>(gedge, 64, w_out, 64, b_out, out,
                                         w_fc1, b_fc1, w_fc2, b_fc2);
}

// round 5
// speedup vs baseline: 2.3732x; 1.0196x over previous
#include <cuda_runtime.h>
#include <cuda_bf16.h>
#include <math.h>

#define HW 65536
#define CMID 64

// ---- scratch (device globals; allocation is forbidden) ----
__device__ float g_y[4 * CMID * HW];      // after input conv1x1  (64 MiB)
__device__ float g_edge[4 * CMID * HW];   // raw edge map         (64 MiB)
__device__ float g_sums[4 * CMID];        // per-(b,c) raw-edge sums
__device__ unsigned int g_maxbits;        // global max (float bits, all >= 0)

// ---- dynamic smem layout (bytes) ----
#define XPITCH 136                        // bf16 elems per X row (128 + 8 pad)
#define WPITCH 72                         // bf16 elems per W row (64 + 8 pad)
#define XH_OFF 0                          // 64 x 136 x 2 = 17408
#define XL_OFF 17408
#define WH_OFF 34816                      // 64 x 72 x 2 = 9216
#define WL_OFF 44032
#define FM_OFF 53248                      // fmul[64] (FOLD only)
#define PL_OFF 53504                      // pooled[64]
#define HH_OFF 53760                      // h[4]
#define SMEM_SZ 53792

// ============================ PTX helpers ==================================
__device__ __forceinline__ unsigned smem_u32(const void* p) {
    unsigned a;
    asm("{ .reg .u64 t; cvta.to.shared.u64 t, %1; cvt.u32.u64 %0, t; }" : "=r"(a) : "l"(p));
    return a;
}
__device__ __forceinline__ void ldsm4t(unsigned& r0, unsigned& r1, unsigned& r2,
                                       unsigned& r3, unsigned a) {
    asm volatile("ldmatrix.sync.aligned.m8n8.x4.trans.shared.b16 {%0,%1,%2,%3}, [%4];"
                 : "=r"(r0), "=r"(r1), "=r"(r2), "=r"(r3) : "r"(a));
}
__device__ __forceinline__ void ldsm4(unsigned& r0, unsigned& r1, unsigned& r2,
                                      unsigned& r3, unsigned a) {
    asm volatile("ldmatrix.sync.aligned.m8n8.x4.shared.b16 {%0,%1,%2,%3}, [%4];"
                 : "=r"(r0), "=r"(r1), "=r"(r2), "=r"(r3) : "r"(a));
}
__device__ __forceinline__ void mma16816(float* d, const unsigned* a,
                                         unsigned b0, unsigned b1) {
    asm volatile("mma.sync.aligned.m16n8k16.row.col.f32.bf16.bf16.f32 "
                 "{%0,%1,%2,%3},{%4,%5,%6,%7},{%8,%9},{%0,%1,%2,%3};"
                 : "+f"(d[0]), "+f"(d[1]), "+f"(d[2]), "+f"(d[3])
                 : "r"(a[0]), "r"(a[1]), "r"(a[2]), "r"(a[3]), "r"(b0), "r"(b1));
}
__device__ __forceinline__ unsigned pk(float a, float b) {
    __nv_bfloat162 t(__float2bfloat16(a), __float2bfloat16(b));
    return *(unsigned*)&t;
}

// ===========================================================================
// conv1x1 via mma.sync bf16 3-term split. Tile: 128 pix x 64 out, K=CHUNKS*64.
// 128 threads / 4 warps; each warp computes m32 (2 m-tiles) x n64 so every
// B fragment feeds 32 pixels (halved L1 ldmatrix traffic vs m16 warps).
// FOLD=1: fuse SE head, fold scale*inv_max into W staging.
// FOLD=0: block 0 additionally zeroes g_sums/g_maxbits for this replay.
template <int CHUNKS, int FOLD>
__global__ void __launch_bounds__(128) k_conv(
    const float* __restrict__ src, int cin,
    const float* __restrict__ wsrc, int wstride,
    const float* __restrict__ bias, float* __restrict__ dst,
    const float* __restrict__ w_fc1, const float* __restrict__ b_fc1,
    const float* __restrict__ w_fc2, const float* __restrict__ b_fc2) {
    extern __shared__ char sm[];
    unsigned smb = smem_u32(sm);
    int tid = threadIdx.x;
    int w   = tid >> 5, lane = tid & 31;

    int t    = blockIdx.x;
    int b    = t >> 9;           // 512 tiles per batch
    int pix0 = (t & 511) << 7;   // 128 pixels per tile

    if (!FOLD && blockIdx.x == 0) {   // init for this replay's edge stage
        g_sums[tid] = 0.f;
        g_sums[tid + 128] = 0.f;
        if (tid == 0) g_maxbits = 0u;
    }

    if (FOLD) {
        float* pooled = (float*)(sm + PL_OFF);
        float* hh     = (float*)(sm + HH_OFF);
        float* fm     = (float*)(sm + FM_OFF);
        float inv = 1.f / (__uint_as_float(g_maxbits) + 1e-8f);
        if (tid < 64) pooled[tid] = g_sums[b * 64 + tid] * (1.f / 65536.f) * inv;
        __syncthreads();
        if (tid < 4) {
            float s = b_fc1[tid];
            for (int cc = 0; cc < 64; ++cc) s = fmaf(w_fc1[tid * 64 + cc], pooled[cc], s);
            hh[tid] = fmaxf(s, 0.f);
        }
        __syncthreads();
        if (tid < 64) {
            float sc = b_fc2[tid];
#pragma unroll
            for (int j = 0; j < 4; ++j) sc = fmaf(w_fc2[tid * 4 + j], hh[j], sc);
            fm[tid] = inv / (1.f + expf(-sc));
        }
        __syncthreads();
    }

    const float* srcb = src + (size_t)b * cin * HW + pix0;

    float acc[2][8][4];
#pragma unroll
    for (int mt = 0; mt < 2; ++mt)
#pragma unroll
        for (int nt = 0; nt < 8; ++nt)
#pragma unroll
            for (int i = 0; i < 4; ++i) acc[mt][nt][i] = 0.f;

    // ldmatrix address components
    int arow  = (lane & 7) + ((lane >> 4) << 3);          // A (trans): k-row within 16
    int acol0 = (w << 5) + (((lane >> 3) & 1) << 3);      // A: pixel col, mt adds +16
    int brow2 = ((lane >> 4) << 3) + (lane & 7);          // B x4: o-row within nt-pair
    int bcol  = ((lane >> 3) & 1) << 3;                   // B: k col (0/8)

    for (int s = 0; s < CHUNKS; ++s) {
        // ---- stage X chunk: gmem [c][pix] fp32 -> smem bf16 hi/lo [c][pix]
        {
            int c = tid >> 1, q = tid & 1;
            const float* xc = srcb + (size_t)(s * 64 + c) * HW;
#pragma unroll
            for (int j = 0; j < 8; ++j) {
                int p = q * 64 + j * 8;
                float4 v0 = *(const float4*)(xc + p);
                float4 v1 = *(const float4*)(xc + p + 4);
                float xs[8] = {v0.x, v0.y, v0.z, v0.w, v1.x, v1.y, v1.z, v1.w};
                float hf[8], lf[8];
#pragma unroll
                for (int i = 0; i < 8; ++i) {
                    hf[i] = __bfloat162float(__float2bfloat16(xs[i]));
                    lf[i] = xs[i] - hf[i];
                }
                uint4 hv = make_uint4(pk(hf[0], hf[1]), pk(hf[2], hf[3]),
                                      pk(hf[4], hf[5]), pk(hf[6], hf[7]));
                uint4 lv = make_uint4(pk(lf[0], lf[1]), pk(lf[2], lf[3]),
                                      pk(lf[4], lf[5]), pk(lf[6], lf[7]));
                *(uint4*)(sm + XH_OFF + (c * XPITCH + p) * 2) = hv;
                *(uint4*)(sm + XL_OFF + (c * XPITCH + p) * 2) = lv;
            }
        }
        // ---- stage W chunk: [64 o][64 c] fp32 -> bf16 hi/lo, vectorized STS.128
        {
            const float* fmp = (const float*)(sm + FM_OFF);
#pragma unroll
            for (int k = 0; k < 4; ++k) {
                int oct = tid + k * 128;          // 512 octets: o = oct>>3, c8 = (oct&7)*8
                int o = oct >> 3, c8 = (oct & 7) * 8;
                const float* wp = wsrc + o * wstride + s * 64 + c8;
                float4 v0 = *(const float4*)wp;
                float4 v1 = *(const float4*)(wp + 4);
                float wv[8] = {v0.x, v0.y, v0.z, v0.w, v1.x, v1.y, v1.z, v1.w};
                if (FOLD) {
#pragma unroll
                    for (int i = 0; i < 8; ++i) wv[i] *= fmp[c8 + i];
                }
                float hf[8], lf[8];
#pragma unroll
                for (int i = 0; i < 8; ++i) {
                    hf[i] = __bfloat162float(__float2bfloat16(wv[i]));
                    lf[i] = wv[i] - hf[i];
                }
                uint4 hv = make_uint4(pk(hf[0], hf[1]), pk(hf[2], hf[3]),
                                      pk(hf[4], hf[5]), pk(hf[6], hf[7]));
                uint4 lv = make_uint4(pk(lf[0], lf[1]), pk(lf[2], lf[3]),
                                      pk(lf[4], lf[5]), pk(lf[6], lf[7]));
                *(uint4*)(sm + WH_OFF + (o * WPITCH + c8) * 2) = hv;
                *(uint4*)(sm + WL_OFF + (o * WPITCH + c8) * 2) = lv;
            }
        }
        __syncthreads();

        // ---- MMA: 4 k-steps of 16
#pragma unroll
        for (int ks = 0; ks < 4; ++ks) {
            unsigned ah[2][4], al[2][4];
#pragma unroll
            for (int mt = 0; mt < 2; ++mt) {
                unsigned aoff = (unsigned)(((ks * 16 + arow) * XPITCH + acol0 + mt * 16) * 2);
                ldsm4t(ah[mt][0], ah[mt][1], ah[mt][2], ah[mt][3], smb + XH_OFF + aoff);
                ldsm4t(al[mt][0], al[mt][1], al[mt][2], al[mt][3], smb + XL_OFF + aoff);
            }
#pragma unroll
            for (int ntp = 0; ntp < 4; ++ntp) {
                unsigned bh[4], bl[4];
                unsigned boff = (unsigned)(((ntp * 16 + brow2) * WPITCH + ks * 16 + bcol) * 2);
                ldsm4(bh[0], bh[1], bh[2], bh[3], smb + WH_OFF + boff);
                ldsm4(bl[0], bl[1], bl[2], bl[3], smb + WL_OFF + boff);
#pragma unroll
                for (int mt = 0; mt < 2; ++mt) {
                    mma16816(acc[mt][ntp * 2],     ah[mt], bh[0], bh[1]);
                    mma16816(acc[mt][ntp * 2],     al[mt], bh[0], bh[1]);
                    mma16816(acc[mt][ntp * 2],     ah[mt], bl[0], bl[1]);
                    mma16816(acc[mt][ntp * 2 + 1], ah[mt], bh[2], bh[3]);
                    mma16816(acc[mt][ntp * 2 + 1], al[mt], bh[2], bh[3]);
                    mma16816(acc[mt][ntp * 2 + 1], ah[mt], bl[2], bl[3]);
                }
            }
        }
        __syncthreads();
    }

    // ---- epilogue: C[m=pix][n=out] fragments -> dst[o][pix] + bias
    int g  = lane >> 2;
    int t2 = (lane & 3) * 2;
#pragma unroll
    for (int mt = 0; mt < 2; ++mt) {
        float* dp = dst + (size_t)b * CMID * HW + pix0 + w * 32 + mt * 16;
#pragma unroll
        for (int nt = 0; nt < 8; ++nt) {
            int o0 = nt * 8 + t2;
            float b0 = __ldg(bias + o0), b1 = __ldg(bias + o0 + 1);
            dp[(size_t)o0 * HW + g]           = acc[mt][nt][0] + b0;
            dp[(size_t)(o0 + 1) * HW + g]     = acc[mt][nt][1] + b1;
            dp[(size_t)o0 * HW + g + 8]       = acc[mt][nt][2] + b0;
            dp[(size_t)(o0 + 1) * HW + g + 8] = acc[mt][nt][3] + b1;
        }
    }
}

// ---------------------------------------------------------------------------
// Fused depthwise stage (identical to the 526us run)
__global__ void __launch_bounds__(256) k_edge() {
    __shared__ float ys[38][40];
    __shared__ float ts[34][40];
    __shared__ float ss[34][36];
    __shared__ float rs[8], rm[8];

    int tid   = threadIdx.x;
    int plane = blockIdx.y;
    int tile  = blockIdx.x;
    int ty0 = (tile >> 3) * 32;
    int tx0 = (tile & 7) * 32;
    const float* yp = g_y + (size_t)plane * HW;

    for (int i = tid; i < 38 * 38; i += 256) {
        int r = i / 38, c = i - r * 38;
        int gy = ty0 - 3 + r, gx = tx0 - 3 + c;
        float v = 0.f;
        if ((unsigned)gy < 256u && (unsigned)gx < 256u) v = yp[gy * 256 + gx];
        ys[r][c] = v;
    }
    __syncthreads();

    float g1 = expf(-0.125f), g2 = expf(-0.5f);
    float sg = 1.f + 2.f * g1 + 2.f * g2;
    float invS = 1.f / (sg * sg);

    for (int i = tid; i < 34 * 38; i += 256) {
        int r = i / 38, c = i - r * 38;
        ts[r][c] = g2 * (ys[r][c] + ys[r + 4][c]) +
                   g1 * (ys[r + 1][c] + ys[r + 3][c]) + ys[r + 2][c];
    }
    __syncthreads();

    for (int i = tid; i < 34 * 34; i += 256) {
        int r = i / 34, c = i - r * 34;
        float v = g2 * (ts[r][c] + ts[r][c + 4]) +
                  g1 * (ts[r][c + 1] + ts[r][c + 3]) + ts[r][c + 2];
        v *= invS;
        int gy = ty0 - 1 + r, gx = tx0 - 1 + c;
        if ((unsigned)gy >= 256u || (unsigned)gx >= 256u) v = 0.f;
        ss[r][c] = v;
    }
    __syncthreads();

    int col = tid & 31;
    int rb  = tid >> 5;
    float lsum = 0.f, lmax = 0.f;
    float* ep = g_edge + (size_t)plane * HW;
#pragma unroll
    for (int q = 0; q < 4; ++q) {
        int r = rb + q * 8;
        float a  = ss[r][col],     bb = ss[r][col + 1],     cv = ss[r][col + 2];
        float d  = ss[r + 1][col], e  = ss[r + 1][col + 1], f  = ss[r + 1][col + 2];
        float g  = ss[r + 2][col], h  = ss[r + 2][col + 1], ii = ss[r + 2][col + 2];
        float g0  = 3.f * (a - cv) + 10.f * (d - f) + 3.f * (g - ii);
        float g90 = 3.f * (a - g)  + 10.f * (bb - h) + 3.f * (cv - ii);
        float lap = 4.f * e - bb - d - f - h;
        float edge = fmaxf(fabsf(g0), fabsf(g90)) + 0.1f * fabsf(lap);
        ep[(ty0 + r) * 256 + tx0 + col] = edge;
        lsum += edge;
        lmax = fmaxf(lmax, edge);
    }

#pragma unroll
    for (int off = 16; off; off >>= 1) {
        lsum += __shfl_down_sync(0xffffffffu, lsum, off);
        lmax = fmaxf(lmax, __shfl_down_sync(0xffffffffu, lmax, off));
    }
    int wid = tid >> 5, lane = tid & 31;
    if (lane == 0) { rs[wid] = lsum; rm[wid] = lmax; }
    __syncthreads();
    if (tid == 0) {
        float s = 0.f, m = 0.f;
#pragma unroll
        for (int w2 = 0; w2 < 8; ++w2) { s += rs[w2]; m = fmaxf(m, rm[w2]); }
        atomicAdd(&g_sums[plane], s);
        atomicMax(&g_maxbits, __float_as_uint(m));
    }
}

// ---------------------------------------------------------------------------
extern "C" void kernel_launch(void* const* d_in, const int* in_sizes, int n_in,
                              void* d_out, int out_size) {
    const float* x     = (const float*)d_in[0];
    const float* w_in  = (const float*)d_in[1];
    const float* b_in  = (const float*)d_in[2];
    const float* w_fc1 = (const float*)d_in[3];
    const float* b_fc1 = (const float*)d_in[4];
    const float* w_fc2 = (const float*)d_in[5];
    const float* b_fc2 = (const float*)d_in[6];
    const float* w_out = (const float*)d_in[7];
    const float* b_out = (const float*)d_in[8];
    float* out = (float*)d_out;

    cudaFuncSetAttribute(k_conv<4, 0>, cudaFuncAttributeMaxDynamicSharedMemorySize, SMEM_SZ);
    cudaFuncSetAttribute(k_conv<1, 1>, cudaFuncAttributeMaxDynamicSharedMemorySize, SMEM_SZ);

    float* gy    = nullptr;
    float* gedge = nullptr;
    cudaGetSymbolAddress((void**)&gy, g_y);
    cudaGetSymbolAddress((void**)&gedge, g_edge);

    // conv_in: K=256 (4 chunks), also zeroes g_sums/g_maxbits for this replay
    k_conv<4, 0><<<2048, 128, SMEM_SZ>>>(x, 256, w_in, 256, b_in, gy,
                                         nullptr, nullptr, nullptr, nullptr);
    k_edge<<<dim3(64, 256), 256>>>();
    // conv_out: K=64, SE head fused + folded into W staging
    k_conv<1, 1><<<2048, 128, SMEM_SZ>>>(gedge, 64, w_out, 64, b_out, out,
                                         w_fc1, b_fc1, w_fc2, b_fc2);
}